// round 2
// baseline (speedup 1.0000x reference)
#include <cuda_runtime.h>
#include <cooperative_groups.h>
namespace cg = cooperative_groups;

#define TSTEPS 512
#define BATCH  256
#define ISZ    64
#define HSZ    256
#define KEXT   (HSZ + ISZ)      // 320
#define BCTA   4                // batch rows per cluster
#define JHALF  128              // output cols per CTA
#define NTH    256
#define KC     8                // K-chunks = warps
#define KROWS  (KEXT / KC)      // 40
#define NBLOCKS ((BATCH / BCTA) * 2)  // 128

__device__ float g_WT[KEXT * HSZ];  // W_ext^T [i][j]
__device__ float g_bias[HSZ];

__global__ void prep_kernel(const float* __restrict__ W_ih,
                            const float* __restrict__ W_hh,
                            const float* __restrict__ b_ih,
                            const float* __restrict__ b_hh) {
    int idx = blockIdx.x * blockDim.x + threadIdx.x;
    int stride = gridDim.x * blockDim.x;
    for (int p = idx; p < KEXT * HSZ; p += stride) {
        int i = p >> 8, j = p & 255;
        g_WT[p] = (i < HSZ) ? W_hh[j * HSZ + i] : W_ih[j * ISZ + (i - HSZ)];
    }
    if (idx < HSZ) g_bias[idx] = b_ih[idx] + b_hh[idx];
}

#define WSM_F (KEXT * JHALF)          // 40960
#define S_F   (KEXT * BCTA)           // 1280
#define RED_F (KC * BCTA * JHALF)     // 4096
#define SMEM_F (WSM_F + 2 * S_F + RED_F + JHALF)
#define SMEM_BYTES (SMEM_F * 4)       // 190976

__global__ void __cluster_dims__(2, 1, 1) __launch_bounds__(NTH, 1)
rnn_kernel(const float* __restrict__ x,
           const float* __restrict__ fc_W,
           const float* __restrict__ fc_b,
           float* __restrict__ out) {
    extern __shared__ float sm[];
    float* Wsm   = sm;
    float* S0    = sm + WSM_F;
    float* red   = sm + WSM_F + 2 * S_F;
    float* biasS = red + RED_F;

    cg::cluster_group cl = cg::this_cluster();
    const int rank = (int)cl.block_rank();
    const int tid  = threadIdx.x;
    const int lane = tid & 31;
    const int kc   = tid >> 5;
    const int b0   = (blockIdx.x >> 1) * BCTA;

    // Weight slice: columns [rank*128, rank*128+128)
    for (int p = tid; p < WSM_F; p += NTH) {
        int i = p >> 7, j = p & 127;
        Wsm[p] = g_WT[(i << 8) + (rank << 7) + j];
    }
    if (tid < JHALF) biasS[tid] = g_bias[(rank << 7) + tid];

    // State buffer 0: h=0, x-part = x_0
    for (int p = tid; p < HSZ * BCTA; p += NTH) S0[p] = 0.f;
    for (int p = tid; p < ISZ * BCTA; p += NTH) {
        int b = p >> 6, i = p & 63;
        S0[((HSZ + i) << 2) + b] = x[(b0 + b) * TSTEPS * ISZ + i];
    }
    __syncthreads();
    cl.sync();

    float* peerS = (float*)cl.map_shared_rank((void*)S0, rank ^ 1);
    const float* xb = x + (size_t)b0 * TSTEPS * ISZ;

    int cur = 0;
    for (int t = 0; t < TSTEPS; ++t) {
        float* scur  = S0 + cur * S_F;
        float* snxt  = S0 + (cur ^ 1) * S_F;
        float* psnxt = peerS + (cur ^ 1) * S_F;

        float a[16];
        #pragma unroll
        for (int q = 0; q < 16; ++q) a[q] = 0.f;

        const float4* W4 = reinterpret_cast<const float4*>(Wsm) + kc * KROWS * 32 + lane;
        const float4* H4 = reinterpret_cast<const float4*>(scur) + kc * KROWS;

        #pragma unroll 8
        for (int ii = 0; ii < KROWS; ++ii) {
            float4 w = W4[ii * 32];   // cols 4*lane..+3, conflict-free
            float4 h = H4[ii];        // 4 batch values, broadcast
            a[0]  += w.x * h.x; a[1]  += w.x * h.y; a[2]  += w.x * h.z; a[3]  += w.x * h.w;
            a[4]  += w.y * h.x; a[5]  += w.y * h.y; a[6]  += w.y * h.z; a[7]  += w.y * h.w;
            a[8]  += w.z * h.x; a[9]  += w.z * h.y; a[10] += w.z * h.z; a[11] += w.z * h.w;
            a[12] += w.w * h.x; a[13] += w.w * h.y; a[14] += w.w * h.z; a[15] += w.w * h.w;
        }

        float4* R4 = reinterpret_cast<float4*>(red);
        #pragma unroll
        for (int b = 0; b < 4; ++b)
            R4[(kc * 4 + b) * 32 + lane] = make_float4(a[b], a[4 + b], a[8 + b], a[12 + b]);
        __syncthreads();

        if (tid < JHALF) {   // warps 0-3: reduce + tanh + publish both halves
            float v0 = biasS[tid], v1 = v0, v2 = v0, v3 = v0;
            #pragma unroll
            for (int k = 0; k < KC; ++k) {
                v0 += red[(k * 4 + 0) * JHALF + tid];
                v1 += red[(k * 4 + 1) * JHALF + tid];
                v2 += red[(k * 4 + 2) * JHALF + tid];
                v3 += red[(k * 4 + 3) * JHALF + tid];
            }
            float4 hn = make_float4(tanhf(v0), tanhf(v1), tanhf(v2), tanhf(v3));
            int jg = (rank << 7) + tid;
            reinterpret_cast<float4*>(snxt)[jg]  = hn;
            reinterpret_cast<float4*>(psnxt)[jg] = hn;   // DSMEM to peer
        } else if (t + 1 < TSTEPS) {   // warps 4-7: prefetch x_{t+1}
            int p = tid - JHALF;
            #pragma unroll
            for (int r = 0; r < 2; ++r) {
                int pp = p + r * JHALF;
                int b = pp >> 6, i = pp & 63;
                snxt[((HSZ + i) << 2) + b] = xb[((size_t)b * TSTEPS + t + 1) * ISZ + i];
            }
        }
        cl.sync();
        cur ^= 1;
    }

    // Final FC (O=1): out[b] = sum_j h_T[j][b] * fc_W[j] + fc_b
    if (rank == 0) {
        float* scur = S0 + cur * S_F;
        float fw = fc_W[tid];
        float4 h = reinterpret_cast<const float4*>(scur)[tid];
        float p0 = h.x * fw, p1 = h.y * fw, p2 = h.z * fw, p3 = h.w * fw;
        #pragma unroll
        for (int off = 16; off; off >>= 1) {
            p0 += __shfl_down_sync(0xffffffffu, p0, off);
            p1 += __shfl_down_sync(0xffffffffu, p1, off);
            p2 += __shfl_down_sync(0xffffffffu, p2, off);
            p3 += __shfl_down_sync(0xffffffffu, p3, off);
        }
        __syncthreads();
        if (lane == 0) {
            red[kc * 4 + 0] = p0; red[kc * 4 + 1] = p1;
            red[kc * 4 + 2] = p2; red[kc * 4 + 3] = p3;
        }
        __syncthreads();
        if (tid < 4) {
            float v = fc_b[0];
            #pragma unroll
            for (int k = 0; k < KC; ++k) v += red[k * 4 + tid];
            out[b0 + tid] = v;
        }
    }
}

extern "C" void kernel_launch(void* const* d_in, const int* in_sizes, int n_in,
                              void* d_out, int out_size) {
    const float* x    = (const float*)d_in[0];
    const float* W_ih = (const float*)d_in[1];
    const float* W_hh = (const float*)d_in[2];
    const float* b_ih = (const float*)d_in[3];
    const float* b_hh = (const float*)d_in[4];
    const float* fc_W = (const float*)d_in[5];
    const float* fc_b = (const float*)d_in[6];
    float* out = (float*)d_out;

    static bool attr_done = false;
    if (!attr_done) {
        cudaFuncSetAttribute(rnn_kernel, cudaFuncAttributeMaxDynamicSharedMemorySize, SMEM_BYTES);
        attr_done = true;
    }

    prep_kernel<<<128, 256>>>(W_ih, W_hh, b_ih, b_hh);
    rnn_kernel<<<NBLOCKS, NTH, SMEM_BYTES>>>(x, fc_W, fc_b, out);
}